// round 17
// baseline (speedup 1.0000x reference)
#include <cuda_runtime.h>

// NonMaximaSuppression2d: x (8,32,512,512) fp32.
// m = max over 8 neighbors (replicate pad), floored at 0 (zeroed center tap).
// out = x * (x > m).
// R16: R9 skeleton (RPT=4, 6-row LDG.128 front batch, launch_bounds(128,12),
// plain stores, launch-indexed grid) + SMEM halo exchange. Key fact: the
// 128-thread block covers the ENTIRE W=512 row, so block edges == image
// edges -> replicate padding is handled by threads 0/127 writing their own
// v.x/v.w into boundary slots. This removes ALL 12 strided edge LDGs per
// tile (each ~5 L1 wavefronts; L1 was 62.6% vs 4 useful wavefronts/row).
// Exchange: 2 STS/row + 1 __syncthreads + LDS at consume time. No warp
// collectives (R10's shuffle failure mode avoided).

#define HH 512
#define WW 512
#define RPT 4           // rows per output strip
#define NROWS (RPT + 2) // 6 rows in the window
#define TPB 128         // threads per block = WW/4 float4 groups
#define SPITCH (TPB + 2)

__device__ __forceinline__ int clampy(int y) { return min(max(y, 0), HH - 1); }

// max of 3 horizontally adjacent values per lane (rows above/below)
__device__ __forceinline__ float4 hmax3(const float4& v, float l, float r) {
    float4 h;
    h.x = fmaxf(fmaxf(l,   v.x), v.y);
    h.y = fmaxf(fmaxf(v.x, v.y), v.z);
    h.z = fmaxf(fmaxf(v.y, v.z), v.w);
    h.w = fmaxf(fmaxf(v.z, v.w), r);
    return h;
}

// max of the 2 horizontal neighbors (center excluded; for the center row)
__device__ __forceinline__ float4 hmax2(const float4& v, float l, float r) {
    float4 h;
    h.x = fmaxf(l,   v.y);
    h.y = fmaxf(v.x, v.z);
    h.z = fmaxf(v.y, v.w);
    h.w = fmaxf(v.z, r);
    return h;
}

__global__ __launch_bounds__(TPB, 12)
void nms2d_kernel(const float* __restrict__ x, float* __restrict__ out) {
    // sw[k][t+1] = v[k].w of thread t  -> l of thread t is sw[k][t]
    // sx[k][t+1] = v[k].x of thread t  -> r of thread t is sx[k][t+2]
    __shared__ float sw[NROWS][SPITCH];
    __shared__ float sx[NROWS][SPITCH];

    const int tiles_per_img = HH / RPT;             // 128
    const int img  = blockIdx.x / tiles_per_img;
    const int tile = blockIdx.x % tiles_per_img;

    const float* in = x   + (size_t)img * HH * WW;
    float*       o  = out + (size_t)img * HH * WW;

    const int t  = threadIdx.x;
    const int c  = t * 4;                           // 0..508
    const int y0 = tile * RPT;

    // front-batch the entire 6-row window: 6 independent LDG.128, NO other
    // global loads (the proven MLP mechanism, untouched)
    float4 v[NROWS];
    #pragma unroll
    for (int k = 0; k < NROWS; k++)
        v[k] = *reinterpret_cast<const float4*>(
            in + (size_t)clampy(y0 - 1 + k) * WW + c);

    // halo exchange: stride-1 STS, conflict-free; image-edge replication by
    // boundary threads writing their own edge element
    #pragma unroll
    for (int k = 0; k < NROWS; k++) {
        sw[k][t + 1] = v[k].w;
        sx[k][t + 1] = v[k].x;
    }
    if (t == 0) {
        #pragma unroll
        for (int k = 0; k < NROWS; k++) sw[k][0] = v[k].x;         // x[-1]=x[0]
    }
    if (t == TPB - 1) {
        #pragma unroll
        for (int k = 0; k < NROWS; k++) sx[k][TPB + 1] = v[k].w;   // x[W]=x[W-1]
    }
    __syncthreads();

    float* op = o + (size_t)y0 * WW + c;

    #pragma unroll
    for (int i = 0; i < RPT; i++) {
        // neighbor values from smem at consume time (LDS hidden by unroll)
        float4 mp = hmax3(v[i],     sw[i][t],     sx[i][t + 2]);
        float4 mc = hmax2(v[i + 1], sw[i + 1][t], sx[i + 1][t + 2]);
        float4 mn = hmax3(v[i + 2], sw[i + 2][t], sx[i + 2][t + 2]);

        // fold the zeroed-center-tap floor (reference inits max at 0)
        float4 m;
        m.x = fmaxf(fmaxf(fmaxf(mp.x, mc.x), mn.x), 0.0f);
        m.y = fmaxf(fmaxf(fmaxf(mp.y, mc.y), mn.y), 0.0f);
        m.z = fmaxf(fmaxf(fmaxf(mp.z, mc.z), mn.z), 0.0f);
        m.w = fmaxf(fmaxf(fmaxf(mp.w, mc.w), mn.w), 0.0f);

        float4 xc = v[i + 1];
        float4 r;
        r.x = (xc.x > m.x) ? xc.x : 0.0f;
        r.y = (xc.y > m.y) ? xc.y : 0.0f;
        r.z = (xc.z > m.z) ? xc.z : 0.0f;
        r.w = (xc.w > m.w) ? xc.w : 0.0f;

        *reinterpret_cast<float4*>(op) = r;
        op += WW;
    }
}

extern "C" void kernel_launch(void* const* d_in, const int* in_sizes, int n_in,
                              void* d_out, int out_size) {
    const float* x = (const float*)d_in[0];
    float* out = (float*)d_out;

    const int n_img = in_sizes[0] / (HH * WW);      // B*C = 256
    const int blocks = n_img * (HH / RPT);          // 32768

    nms2d_kernel<<<blocks, TPB>>>(x, out);
}